// round 17
// baseline (speedup 1.0000x reference)
#include <cuda_runtime.h>

// ============================================================================
// EDF ensemble detection fusion, N = 8192.  R15 = R12 (passing, 82.4us) +
//  - PDL (programmatic dependent launch) on all 6 kernels: launch setup
//    overlaps predecessor execution; cudaGridDependencySynchronize() at each
//    kernel top preserves exact serial semantics (full completion + membar)
//  - k_edges: two x-rows per warp (one B load serves two IoU evals)
//  - float4 box loads in prep kernels
//
// Launches (all PDL-chained):
//   K0 k_init    [64 blk] score-bucket + x-bin histograms, scratch reset
//   K1 k_scan    [1 blk]  scans both histograms; zero cursors/hist/ecnt
//   K2 k_scatter [64 blk] scatter score keys + clipped float4 boxes
//   K3 k_rankg   [64 blk] exact stable rank -> score SoA + xord
//   K4 k_edges   [512 blk] 2 rows/warp exact IoU, pruned ranges
//   K5 k_post    [1 blk]  CSR + cached-neighbor fixpoint + stats + output
// ============================================================================

#define NN 8192
#define ECAP 60000
#define BINS 256
#define SBK 1024
#define INV_BINW (256.0f / 1920.0f)
#define W_IMG 1920.0f
#define H_IMG 1080.0f

__device__ int    g_histS[SBK], g_offS[SBK + 1], g_curS[SBK];
__device__ int    g_histX[BINS], g_offX[BINS + 1], g_curX[BINS];
__device__ unsigned long long g_bk[NN];   // bucket-ordered score keys
__device__ int    g_posx[NN];             // original i -> x-bin position
__device__ int    g_binOff[BINS + 1];
__device__ float  g_bx1[NN], g_by1[NN], g_bx2[NN], g_by2[NN], g_s[NN];
__device__ float4 g_xs4[NN];              // x-bin-ordered clipped boxes
__device__ int    g_xord[NN];             // x-bin position -> score rank
__device__ int    g_degIn[NN];
__device__ int    g_cursor[NN];
__device__ int    g_eh[ECAP], g_ej[ECAP], g_inList[ECAP];
__device__ int    g_ecnt;
__device__ int    g_count[NN];
__device__ float  g_sum[NN];
__device__ unsigned g_maxY2[NN];
__device__ int    g_first[NN];

// Score bucket: monotone map of u = ~bits(score) (descending-score order).
__device__ __forceinline__ int score_bucket(float s) {
    const unsigned u0 = ~__float_as_uint(1.0f);
    const float sscale = (float)SBK /
                         (float)(~__float_as_uint(0.3f) - u0);
    unsigned u = ~__float_as_uint(s);
    int d = (int)(u - u0);
    return (d <= 0) ? 0 : min(SBK - 1, (int)((float)d * sscale));
}

__device__ __forceinline__ float4 clip_box(float4 b) {
    return make_float4(fminf(fmaxf(b.x, 0.0f), W_IMG),
                       fminf(fmaxf(b.y, 0.0f), H_IMG),
                       fminf(fmaxf(b.z, 0.0f), W_IMG),
                       fminf(fmaxf(b.w, 0.0f), H_IMG));
}

// ---------------------------------------------------------------------------
// K0: histograms (global atomics) + per-replay scratch reset.
// ---------------------------------------------------------------------------
__global__ void k_init(const float4* __restrict__ boxes4,
                       const float* __restrict__ scores) {
    cudaGridDependencySynchronize();
    int i = blockIdx.x * blockDim.x + threadIdx.x;
    if (i >= NN) return;
    int sb = score_bucket(scores[i]);
    float x1 = fminf(fmaxf(boxes4[i].x, 0.0f), W_IMG);
    int xb = min((int)(x1 * INV_BINW), BINS - 1);
    atomicAdd(&g_histS[sb], 1);
    atomicAdd(&g_histX[xb], 1);
    g_degIn[i]  = 0;
    g_cursor[i] = 0;
    g_count[i]  = 0;
    g_sum[i]    = 0.0f;
    g_maxY2[i]  = 0u;                  // y2 >= 0 -> 0-bits is a valid -inf
    g_first[i]  = NN;
}

// ---------------------------------------------------------------------------
// K1: single block scans both histograms -> offsets; zeroes hist (next
// replay), cursors (this replay's scatter) and ecnt.
// ---------------------------------------------------------------------------
__global__ void __launch_bounds__(1024)
k_scan() {
    cudaGridDependencySynchronize();
    __shared__ int sS[SBK];
    __shared__ int sX[BINS];
    int tid = threadIdx.x;

    int v = g_histS[tid];
    sS[tid] = v;
    __syncthreads();
    for (int o = 1; o < SBK; o <<= 1) {
        int t = (tid >= o) ? sS[tid - o] : 0;
        __syncthreads();
        sS[tid] += t;
        __syncthreads();
    }
    g_offS[tid] = sS[tid] - v;
    if (tid == SBK - 1) g_offS[SBK] = sS[tid];
    g_histS[tid] = 0;
    g_curS[tid]  = 0;

    int v2 = (tid < BINS) ? g_histX[tid] : 0;
    if (tid < BINS) sX[tid] = v2;
    __syncthreads();
    for (int o = 1; o < BINS; o <<= 1) {
        int t = (tid >= o && tid < BINS) ? sX[tid - o] : 0;
        __syncthreads();
        if (tid < BINS) sX[tid] += t;
        __syncthreads();
    }
    if (tid < BINS) {
        int ex = sX[tid] - v2;
        g_offX[tid] = ex;
        g_binOff[tid] = ex;
        if (tid == BINS - 1) { g_offX[BINS] = sX[tid]; g_binOff[BINS] = sX[tid]; }
        g_histX[tid] = 0;
        g_curX[tid]  = 0;
    }
    if (tid == 0) g_ecnt = 0;
}

// ---------------------------------------------------------------------------
// K2: scatter score keys into bucket order; clipped float4 boxes into x-bins.
// ---------------------------------------------------------------------------
__global__ void k_scatter(const float4* __restrict__ boxes4,
                          const float* __restrict__ scores) {
    cudaGridDependencySynchronize();
    int i = blockIdx.x * blockDim.x + threadIdx.x;
    if (i >= NN) return;
    unsigned u = ~__float_as_uint(scores[i]);
    int sb = score_bucket(scores[i]);
    int ps = g_offS[sb] + atomicAdd(&g_curS[sb], 1);
    g_bk[ps] = (((unsigned long long)u) << 32) | (unsigned)i;

    float4 cb = clip_box(boxes4[i]);
    int xb = min((int)(cb.x * INV_BINW), BINS - 1);
    int px = g_offX[xb] + atomicAdd(&g_curX[xb], 1);
    g_xs4[px] = cb;
    g_posx[i] = px;
}

// ---------------------------------------------------------------------------
// K3: exact stable rank (bucket offset + in-bucket count of smaller unique
// keys) == stable argsort(-scores) permutation. Writes score-sorted SoA
// and xord mapping.
// ---------------------------------------------------------------------------
__global__ void k_rankg(const float4* __restrict__ boxes4,
                        const float* __restrict__ scores) {
    cudaGridDependencySynchronize();
    int i = blockIdx.x * blockDim.x + threadIdx.x;
    if (i >= NN) return;
    unsigned u = ~__float_as_uint(scores[i]);
    int sb = score_bucket(scores[i]);
    unsigned long long my = (((unsigned long long)u) << 32) | (unsigned)i;
    int st = g_offS[sb], en = g_offS[sb + 1];
    int c = 0;
#pragma unroll 4
    for (int t = st; t < en; t++) c += (g_bk[t] < my) ? 1 : 0;
    int r = st + c;

    float4 cb = clip_box(boxes4[i]);
    g_bx1[r] = cb.x; g_by1[r] = cb.y; g_bx2[r] = cb.z; g_by2[r] = cb.w;
    g_s[r] = scores[i];
    g_xord[g_posx[i]] = r;
}

// ---------------------------------------------------------------------------
// Exact reference IoU test; on pass, record edge (score-index space, i<j).
// ---------------------------------------------------------------------------
__device__ __forceinline__ void iou_emit(float4 A, float aa, int pa,
                                         float4 B, int bpos) {
    float ix1 = fmaxf(A.x, B.x);
    float iy1 = fmaxf(A.y, B.y);
    float ix2 = fminf(A.z, B.z);
    float iy2 = fminf(A.w, B.w);
    float iw = fmaxf(__fadd_rn(__fsub_rn(ix2, ix1), 1.0f), 0.0f);
    float ih = fmaxf(__fadd_rn(__fsub_rn(iy2, iy1), 1.0f), 0.0f);
    float inter = __fmul_rn(iw, ih);
    if (inter > 0.0f) {
        float ab = __fmul_rn(__fadd_rn(__fsub_rn(B.z, B.x), 1.0f),
                             __fadd_rn(__fsub_rn(B.w, B.y), 1.0f));
        float uni = __fsub_rn(__fadd_rn(aa, ab), inter);
        if (__fdiv_rn(inter, uni) > 0.5f) {
            int pb = g_xord[bpos];
            int i = min(pa, pb);
            int j = max(pa, pb);
            int e = atomicAdd(&g_ecnt, 1);
            if (e < ECAP) {
                g_eh[e] = i;
                g_ej[e] = j;
                atomicAdd(&g_degIn[j], 1);
            }
        }
    }
}

// ---------------------------------------------------------------------------
// K4: TWO x-rows per warp (a0=2w, a1=2w+1). One B load serves both rows.
// Row a0: candidates b in (a0, end0) with x1_b <= x2_a0 + 2.
// Row a1: candidates b in (a1, end1), i.e. b != a1 since loop starts a0+1.
// Conservative superset; exact reference arithmetic decides each pair.
// ---------------------------------------------------------------------------
__global__ void k_edges() {
    cudaGridDependencySynchronize();
    int w = (blockIdx.x * blockDim.x + threadIdx.x) >> 5;
    int lane = threadIdx.x & 31;
    if (w >= NN / 2) return;
    int a0 = w * 2, a1 = a0 + 1;
    float4 A0 = g_xs4[a0];
    float4 A1 = g_xs4[a1];
    int pa0 = g_xord[a0], pa1 = g_xord[a1];
    float aa0 = __fmul_rn(__fadd_rn(__fsub_rn(A0.z, A0.x), 1.0f),
                          __fadd_rn(__fsub_rn(A0.w, A0.y), 1.0f));
    float aa1 = __fmul_rn(__fadd_rn(__fsub_rn(A1.z, A1.x), 1.0f),
                          __fadd_rn(__fsub_rn(A1.w, A1.y), 1.0f));
    float th0 = A0.z + 2.0f;
    float th1 = A1.z + 2.0f;
    int bm0 = min((int)(th0 * INV_BINW), BINS - 1);
    int bm1 = min((int)(th1 * INV_BINW), BINS - 1);
    int end0 = g_binOff[bm0 + 1];
    int end1 = g_binOff[bm1 + 1];
    int endMax = max(end0, end1);

    for (int b0 = a0 + 1; b0 < endMax; b0 += 32) {
        int b = b0 + lane;
        if (b < endMax) {
            float4 B = g_xs4[b];
            if (b < end0 && B.x <= th0)
                iou_emit(A0, aa0, pa0, B, b);
            if (b != a1 && b < end1 && B.x <= th1)
                iou_emit(A1, aa1, pa1, B, b);
        }
    }
}

// ---------------------------------------------------------------------------
// K5: single-block tail [R12 verbatim]. CSR scan+fill, greedy-cluster
// fixpoint with register-cached neighbor lists, stats, first-pick, output.
// ---------------------------------------------------------------------------
__global__ void __launch_bounds__(1024)
k_post(const int* __restrict__ nmp, float* __restrict__ out, int out_size) {
    cudaGridDependencySynchronize();
    __shared__ short          s_sc[NN];      // -1 undecided / cluster id
    __shared__ unsigned short s_off[NN];     // CSR starts (total < 65536)
    __shared__ int            s_sums[1024];
    __shared__ int            s_total, s_ch;
    int tid = threadIdx.x;

    // (a) scan of g_degIn -> s_off (exclusive), s_total
    {
        int base = tid * 8;
        int ex[8];
        int sum = 0;
#pragma unroll
        for (int r = 0; r < 8; r++) {
            int v = g_degIn[base + r];
            ex[r] = sum;
            sum += v;
        }
        s_sums[tid] = sum;
        __syncthreads();
        for (int off = 1; off < 1024; off <<= 1) {
            int t = (tid >= off) ? s_sums[tid - off] : 0;
            __syncthreads();
            s_sums[tid] += t;
            __syncthreads();
        }
        int blockEx = s_sums[tid] - sum;
#pragma unroll
        for (int r = 0; r < 8; r++)
            s_off[base + r] = (unsigned short)(blockEx + ex[r]);
        if (tid == 1023) s_total = blockEx + sum;
    }
    __syncthreads();
    int total = s_total;

    // (b) CSR fill
    {
        int ec = g_ecnt;
        if (ec > ECAP) ec = ECAP;
        for (int e = tid; e < ec; e += 1024) {
            int j = g_ej[e];
            int pos = (int)s_off[j] + atomicAdd(&g_cursor[j], 1);
            g_inList[pos] = g_eh[e];
        }
    }
    __syncthreads();

    // (c) fixpoint with cached neighbors. Thread owns nodes i = r*1024+tid.
    short nbr[8][8];
    unsigned char ndeg[8];
    unsigned undecided = 0;

#pragma unroll
    for (int r = 0; r < 8; r++) {
        int i = r * 1024 + tid;
        int st = s_off[i];
        int en = (i < NN - 1) ? (int)s_off[i + 1] : total;
        int deg = en - st;
        ndeg[r] = (unsigned char)min(deg, 255);
        if (deg == 0) {
            s_sc[i] = (short)i;
        } else {
            s_sc[i] = -1;
            undecided |= (1u << r);
            int kmax = min(deg, 8);
            for (int k = 0; k < kmax; k++)
                nbr[r][k] = (short)g_inList[st + k];
        }
    }
    __syncthreads();

    for (int round = 0; round < 1024; round++) {
        if (tid == 0) s_ch = 0;
        __syncthreads();
        unsigned rem = undecided;
        while (rem) {
            int r = __ffs(rem) - 1;
            rem &= rem - 1;
            int i = r * 1024 + tid;
            int deg = ndeg[r];
            int m = 0x7fffffff, u = 0x7fffffff;
            int kmax = min(deg, 8);
            for (int k = 0; k < kmax; k++) {
                int h = nbr[r][k];
                int c = s_sc[h];
                if (c == h)      m = min(m, h);
                else if (c < 0)  u = min(u, h);
            }
            if (deg > 8) {
                int st = s_off[i];
                int en = (i < NN - 1) ? (int)s_off[i + 1] : total;
                for (int p = st + 8; p < en; p++) {
                    int h = g_inList[p];
                    int c = s_sc[h];
                    if (c == h)      m = min(m, h);
                    else if (c < 0)  u = min(u, h);
                }
            }
            if (m < u) {
                s_sc[i] = (short)m;
                undecided &= ~(1u << r);
                s_ch = 1;
            } else if (u == 0x7fffffff) {
                s_sc[i] = (short)i;
                undecided &= ~(1u << r);
                s_ch = 1;
            }
        }
        __syncthreads();
        int done = (s_ch == 0);
        __syncthreads();
        if (done) break;
    }

    // (d) stats
    for (int j = tid; j < NN; j += 1024) {
        int c = s_sc[j];
        atomicAdd(&g_count[c], 1);
        atomicAdd(&g_sum[c], g_s[j]);
        atomicMax(&g_maxY2[c], __float_as_uint(g_by2[j]));
    }
    __syncthreads();

    // (e) first pick
    for (int j = tid; j < NN; j += 1024) {
        int c = s_sc[j];
        if (g_by2[j] >= __uint_as_float(g_maxY2[c])) atomicMin(&g_first[c], j);
    }
    __syncthreads();

    // (f) output: out[0..5N) = (N,5) rows, out[5N..6N) = keep as 0/1 floats.
    int nm = nmp[0];
    if (nm < 1 || nm > 1000000) {
        float f = __int_as_float(nm);
        nm = (int)f;
        if (nm < 1) nm = 1;
    }
    for (int j = tid; j < NN; j += 1024) {
        int c = s_sc[j];
        bool keep = (j == g_first[c]) && (3 * g_count[c] >= nm);
        float r0 = 0.f, r1 = 0.f, r2 = 0.f, r3 = 0.f, r4 = 0.f, kf = 0.f;
        if (keep) {
            r0 = g_bx1[j]; r1 = g_by1[j]; r2 = g_bx2[j]; r3 = g_by2[j];
            r4 = __fdiv_rn(g_sum[c], (float)nm);
            kf = 1.0f;
        }
        long long obase = (long long)j * 5;
        if (obase + 4 < out_size) {
            out[obase + 0] = r0; out[obase + 1] = r1; out[obase + 2] = r2;
            out[obase + 3] = r3; out[obase + 4] = r4;
        }
        long long kpos = (long long)NN * 5 + j;
        if (kpos < out_size) out[kpos] = kf;
    }
}

// ---------------------------------------------------------------------------
// PDL launch helper: programmatic stream serialization on the default stream.
// Semantics identical to serial launches (dep-sync waits for full predecessor
// completion incl. membar); only launch latency overlaps.
// ---------------------------------------------------------------------------
template <typename... Args>
static void pdl_launch(void (*kern)(Args...), dim3 grid, dim3 block,
                       Args... args) {
    cudaLaunchConfig_t cfg = {};
    cfg.gridDim = grid;
    cfg.blockDim = block;
    cfg.dynamicSmemBytes = 0;
    cfg.stream = 0;
    cudaLaunchAttribute attr[1];
    attr[0].id = cudaLaunchAttributeProgrammaticStreamSerialization;
    attr[0].val.programmaticStreamSerializationAllowed = 1;
    cfg.attrs = attr;
    cfg.numAttrs = 1;
    cudaLaunchKernelEx(&cfg, kern, args...);
}

extern "C" void kernel_launch(void* const* d_in, const int* in_sizes, int n_in,
                              void* d_out, int out_size) {
    const float* boxes  = nullptr;
    const float* scores = nullptr;
    const int*   nmp    = nullptr;
    for (int k = 0; k < n_in; k++) {
        if (in_sizes[k] == NN * 4)      boxes  = (const float*)d_in[k];
        else if (in_sizes[k] == NN)     scores = (const float*)d_in[k];
        else if (in_sizes[k] == 1)      nmp    = (const int*)d_in[k];
    }
    if (!boxes)  boxes  = (const float*)d_in[0];
    if (!scores) scores = (const float*)d_in[1];
    if (!nmp)    nmp    = (const int*)d_in[n_in - 1];

    const float4* boxes4 = (const float4*)boxes;
    float* out = (float*)d_out;

    pdl_launch(k_init,    dim3(64),  dim3(128), boxes4, scores);
    pdl_launch(k_scan,    dim3(1),   dim3(1024));
    pdl_launch(k_scatter, dim3(64),  dim3(128), boxes4, scores);
    pdl_launch(k_rankg,   dim3(64),  dim3(128), boxes4, scores);
    pdl_launch(k_edges,   dim3(512), dim3(256));   // 4096 warps, 2 rows/warp
    pdl_launch(k_post,    dim3(1),   dim3(1024), nmp, out, out_size);
}